// round 14
// baseline (speedup 1.0000x reference)
#include <cuda_runtime.h>

#define D 64
#define D4 16   // float4s per row

static const int NU = 30000, NB = 10000, NI = 60000;

// Concatenated node space: UB(40000) | UI(90000) | BI(70000) | UIagg(30000) | BIagg(10000)
#define TOT_NODES 240000
#define TOT_EDGES 5600000
#define SCAN_TB 512
#define MAX_BLKS 512

// Static device scratch (allocation-free rule). Per-graph feat ping-pongs so
// the three propagations can run CONCURRENTLY on separate streams.
__device__ float g_ub_f1[40000 * 64];
__device__ float g_ub_f2[40000 * 64];
__device__ float g_ui_f1[90000 * 64];
__device__ float g_ui_f2[90000 * 64];
__device__ float g_bi_f1[70000 * 64];
__device__ float g_bi_f2[70000 * 64];
__device__ float g_ub_acc[40000 * 64];
__device__ float g_ui_acc[90000 * 64];
__device__ float g_bi_acc[70000 * 64];
__device__ int   g_cnt   [TOT_NODES];
__device__ int   g_rowptr[TOT_NODES + 1];
__device__ int2  g_colval[TOT_EDGES];
__device__ int   g_partials[MAX_BLKS];

struct GraphSet {
    const int*   rows[5];
    const int*   cols[5];
    const float* vals[5];
    int e_base[6];
    int n_base[6];
};

// ---------------------------------------------------------------------------
__global__ void k_zero_int(int* __restrict__ p, int n) {
    int i = blockIdx.x * blockDim.x + threadIdx.x;
    if (i < n) p[i] = 0;
}

__global__ void k_hist_all(GraphSet gs, int tot_e, int stride, int* __restrict__ cnt) {
    int t = blockIdx.x * blockDim.x + threadIdx.x;
    if (t >= stride) return;
    #pragma unroll
    for (int k = 0; k < 2; k++) {
        int i = t + k * stride;
        if (i < tot_e) {
            int g = 0;
            #pragma unroll
            for (int m = 1; m < 5; m++) if (i >= gs.e_base[m]) g = m;
            int ei = i - gs.e_base[g];
            atomicAdd(&cnt[gs.n_base[g] + gs.rows[g][ei]], 1);
        }
    }
}

__global__ void k_partial(const int* __restrict__ cnt, int n, int* __restrict__ partials) {
    __shared__ int s[SCAN_TB];
    int i = blockIdx.x * SCAN_TB + threadIdx.x;
    int t = threadIdx.x;
    s[t] = (i < n) ? cnt[i] : 0;
    __syncthreads();
    for (int o = SCAN_TB / 2; o; o >>= 1) {
        if (t < o) s[t] += s[t + o];
        __syncthreads();
    }
    if (t == 0) partials[blockIdx.x] = s[0];
}

__global__ void k_scan_partials(int* __restrict__ p, int nblk) {
    __shared__ int s[MAX_BLKS];
    int t = threadIdx.x;
    s[t] = (t < nblk) ? p[t] : 0;
    __syncthreads();
    for (int o = 1; o < MAX_BLKS; o <<= 1) {
        int v = (t >= o) ? s[t - o] : 0;
        __syncthreads();
        s[t] += v;
        __syncthreads();
    }
    if (t < nblk) p[t] = (t ? s[t - 1] : 0);
}

__global__ void k_scan_final(int* __restrict__ cnt, int n,
                             const int* __restrict__ partials, int* __restrict__ rowptr) {
    __shared__ int s[SCAN_TB];
    int i = blockIdx.x * SCAN_TB + threadIdx.x;
    int t = threadIdx.x;
    int c = (i < n) ? cnt[i] : 0;
    s[t] = c;
    __syncthreads();
    for (int o = 1; o < SCAN_TB; o <<= 1) {
        int v = (t >= o) ? s[t - o] : 0;
        __syncthreads();
        s[t] += v;
        __syncthreads();
    }
    int start = partials[blockIdx.x] + s[t] - c;   // exclusive
    if (i < n) {
        rowptr[i] = start;
        cnt[i] = start;
        if (i == n - 1) rowptr[n] = start + c;
    }
}

__global__ void k_scatter_all(GraphSet gs, int tot_e, int stride,
                              int* __restrict__ pos, int2* __restrict__ colval) {
    int t = blockIdx.x * blockDim.x + threadIdx.x;
    if (t >= stride) return;
    int i0 = t, i1 = t + stride, i2 = t + 2 * stride, i3 = t + 3 * stride;
    int g0 = 0, g1 = 0, g2 = 0, g3 = 0;
    #pragma unroll
    for (int m = 1; m < 5; m++) {
        if (i0 >= gs.e_base[m]) g0 = m;
        if (i1 >= gs.e_base[m]) g1 = m;
        if (i2 >= gs.e_base[m]) g2 = m;
        if (i3 >= gs.e_base[m]) g3 = m;
    }
    bool v0 = i0 < tot_e, v1 = i1 < tot_e, v2 = i2 < tot_e, v3 = i3 < tot_e;
    int e0 = i0 - gs.e_base[g0], e1 = i1 - gs.e_base[g1];
    int e2 = i2 - gs.e_base[g2], e3 = i3 - gs.e_base[g3];
    int p0 = 0, p1 = 0, p2 = 0, p3 = 0;
    if (v0) p0 = atomicAdd(&pos[gs.n_base[g0] + gs.rows[g0][e0]], 1);
    if (v1) p1 = atomicAdd(&pos[gs.n_base[g1] + gs.rows[g1][e1]], 1);
    if (v2) p2 = atomicAdd(&pos[gs.n_base[g2] + gs.rows[g2][e2]], 1);
    if (v3) p3 = atomicAdd(&pos[gs.n_base[g3] + gs.rows[g3][e3]], 1);
    if (v0) colval[p0] = make_int2(gs.cols[g0][e0], __float_as_int(gs.vals[g0][e0]));
    if (v1) colval[p1] = make_int2(gs.cols[g1][e1], __float_as_int(gs.vals[g1][e1]));
    if (v2) colval[p2] = make_int2(gs.cols[g2][e2], __float_as_int(gs.vals[g2][e2]));
    if (v3) colval[p3] = make_int2(gs.cols[g3][e3], __float_as_int(gs.vals[g3][e3]));
}

// ---------------------------------------------------------------------------
__global__ void k_init(const float4* __restrict__ a, const float4* __restrict__ b,
                       int na_v4, int tot_v4,
                       const float* __restrict__ coefs,
                       float4* __restrict__ feat, float4* __restrict__ acc) {
    int i = blockIdx.x * blockDim.x + threadIdx.x;
    if (i >= tot_v4) return;
    float4 v = (i < na_v4) ? a[i] : b[i - na_v4];
    float c = coefs[0];
    feat[i] = v;
    acc[i] = make_float4(c * v.x, c * v.y, c * v.z, c * v.w);
}

__device__ __forceinline__ void fma4(float4& a, float v, float4 x) {
    a.x += v * x.x; a.y += v * x.y; a.z += v * x.z; a.w += v * x.w;
}

__global__ void k_spmm_csr(const int* __restrict__ rowptr, const int2* __restrict__ colval,
                           const float4* __restrict__ feat, int n_rows,
                           float4* __restrict__ feat_out, float4* __restrict__ acc_buf,
                           const float* __restrict__ coefs, int li) {
    int w   = (blockIdx.x * blockDim.x + threadIdx.x) >> 5;
    int lid = threadIdx.x & 31;
    if (w >= n_rows) return;
    int half = lid >> 4, q = lid & 15;
    int s = rowptr[w], e = rowptr[w + 1];
    float4 a0 = make_float4(0.f, 0.f, 0.f, 0.f);
    float4 a1 = make_float4(0.f, 0.f, 0.f, 0.f);
    int j = s + half;
    for (; j + 6 < e; j += 8) {
        int2 c0 = colval[j], c1 = colval[j + 2], c2 = colval[j + 4], c3 = colval[j + 6];
        float4 x0 = feat[c0.x * D4 + q];
        float4 x1 = feat[c1.x * D4 + q];
        float4 x2 = feat[c2.x * D4 + q];
        float4 x3 = feat[c3.x * D4 + q];
        fma4(a0, __int_as_float(c0.y), x0);
        fma4(a1, __int_as_float(c1.y), x1);
        fma4(a0, __int_as_float(c2.y), x2);
        fma4(a1, __int_as_float(c3.y), x3);
    }
    for (; j < e; j += 2) {
        int2 cv = colval[j];
        fma4(a0, __int_as_float(cv.y), feat[cv.x * D4 + q]);
    }
    float4 acc = make_float4(a0.x + a1.x, a0.y + a1.y, a0.z + a1.z, a0.w + a1.w);
    acc.x += __shfl_xor_sync(0xffffffffu, acc.x, 16);
    acc.y += __shfl_xor_sync(0xffffffffu, acc.y, 16);
    acc.z += __shfl_xor_sync(0xffffffffu, acc.z, 16);
    acc.w += __shfl_xor_sync(0xffffffffu, acc.w, 16);
    float ss = acc.x * acc.x + acc.y * acc.y + acc.z * acc.z + acc.w * acc.w;
    #pragma unroll
    for (int o = 8; o; o >>= 1) ss += __shfl_xor_sync(0xffffffffu, ss, o);
    float k = coefs[li] / fmaxf(sqrtf(ss), 1e-12f);
    if (half == 0) {
        int idx = w * D4 + q;
        feat_out[idx] = acc;
        float4 a = acc_buf[idx];
        a.x += k * acc.x; a.y += k * acc.y; a.z += k * acc.z; a.w += k * acc.w;
        acc_buf[idx] = a;
    }
}

__global__ void k_out_users(const int* __restrict__ rowptr, const int2* __restrict__ colval,
                            const float4* __restrict__ bi_acc,
                            const float4* __restrict__ ub_acc,
                            const float4* __restrict__ ui_acc,
                            const float* __restrict__ modal, float4* __restrict__ out) {
    int w   = (blockIdx.x * blockDim.x + threadIdx.x) >> 5;
    int lid = threadIdx.x & 31;
    if (w >= NU) return;
    int half = lid >> 4, q = lid & 15;
    int s = rowptr[w], e = rowptr[w + 1];
    float4 a0 = make_float4(0.f, 0.f, 0.f, 0.f);
    float4 a1 = make_float4(0.f, 0.f, 0.f, 0.f);
    int j = s + half;
    for (; j + 6 < e; j += 8) {
        int2 c0 = colval[j], c1 = colval[j + 2], c2 = colval[j + 4], c3 = colval[j + 6];
        float4 x0 = bi_acc[(NB + c0.x) * D4 + q];
        float4 x1 = bi_acc[(NB + c1.x) * D4 + q];
        float4 x2 = bi_acc[(NB + c2.x) * D4 + q];
        float4 x3 = bi_acc[(NB + c3.x) * D4 + q];
        fma4(a0, __int_as_float(c0.y), x0);
        fma4(a1, __int_as_float(c1.y), x1);
        fma4(a0, __int_as_float(c2.y), x2);
        fma4(a1, __int_as_float(c3.y), x3);
    }
    for (; j < e; j += 2) {
        int2 cv = colval[j];
        fma4(a0, __int_as_float(cv.y), bi_acc[(NB + cv.x) * D4 + q]);
    }
    float4 agg = make_float4(a0.x + a1.x, a0.y + a1.y, a0.z + a1.z, a0.w + a1.w);
    agg.x += __shfl_xor_sync(0xffffffffu, agg.x, 16);
    agg.y += __shfl_xor_sync(0xffffffffu, agg.y, 16);
    agg.z += __shfl_xor_sync(0xffffffffu, agg.z, 16);
    agg.w += __shfl_xor_sync(0xffffffffu, agg.w, 16);
    if (half == 0) {
        float m0 = modal[0], m1 = modal[1], m2 = modal[2];
        int idx = w * D4 + q;
        float4 u = ub_acc[idx];
        float4 t = ui_acc[idx];
        out[idx] = make_float4(m0 * u.x + m1 * t.x + m2 * agg.x,
                               m0 * u.y + m1 * t.y + m2 * agg.y,
                               m0 * u.z + m1 * t.z + m2 * agg.z,
                               m0 * u.w + m1 * t.w + m2 * agg.w);
    }
}

__global__ void k_out_bundles(const int* __restrict__ rowptr, const int2* __restrict__ colval,
                              const float4* __restrict__ ui_acc,
                              const float4* __restrict__ ub_acc,
                              const float4* __restrict__ bi_acc,
                              const float* __restrict__ modal, float4* __restrict__ out) {
    int w   = (blockIdx.x * blockDim.x + threadIdx.x) >> 5;
    int lid = threadIdx.x & 31;
    if (w >= NB) return;
    int half = lid >> 4, q = lid & 15;
    int s = rowptr[w], e = rowptr[w + 1];
    float4 a0 = make_float4(0.f, 0.f, 0.f, 0.f);
    float4 a1 = make_float4(0.f, 0.f, 0.f, 0.f);
    int j = s + half;
    for (; j + 6 < e; j += 8) {
        int2 c0 = colval[j], c1 = colval[j + 2], c2 = colval[j + 4], c3 = colval[j + 6];
        float4 x0 = ui_acc[(NU + c0.x) * D4 + q];
        float4 x1 = ui_acc[(NU + c1.x) * D4 + q];
        float4 x2 = ui_acc[(NU + c2.x) * D4 + q];
        float4 x3 = ui_acc[(NU + c3.x) * D4 + q];
        fma4(a0, __int_as_float(c0.y), x0);
        fma4(a1, __int_as_float(c1.y), x1);
        fma4(a0, __int_as_float(c2.y), x2);
        fma4(a1, __int_as_float(c3.y), x3);
    }
    for (; j < e; j += 2) {
        int2 cv = colval[j];
        fma4(a0, __int_as_float(cv.y), ui_acc[(NU + cv.x) * D4 + q]);
    }
    float4 agg = make_float4(a0.x + a1.x, a0.y + a1.y, a0.z + a1.z, a0.w + a1.w);
    agg.x += __shfl_xor_sync(0xffffffffu, agg.x, 16);
    agg.y += __shfl_xor_sync(0xffffffffu, agg.y, 16);
    agg.z += __shfl_xor_sync(0xffffffffu, agg.z, 16);
    agg.w += __shfl_xor_sync(0xffffffffu, agg.w, 16);
    if (half == 0) {
        float m0 = modal[0], m1 = modal[1], m2 = modal[2];
        float4 u = ub_acc[(NU + w) * D4 + q];
        float4 t = bi_acc[w * D4 + q];
        out[(NU + w) * D4 + q] =
            make_float4(m0 * u.x + m2 * t.x + m1 * agg.x,
                        m0 * u.y + m2 * t.y + m1 * agg.y,
                        m0 * u.z + m2 * t.z + m1 * agg.z,
                        m0 * u.w + m2 * t.w + m1 * agg.w);
    }
}

// ---------------------------------------------------------------------------
static inline int ceil_div(int a, int b) { return (a + b - 1) / b; }

extern "C" void kernel_launch(void* const* d_in, const int* in_sizes, int n_in,
                              void* d_out, int out_size) {
    const float* users   = (const float*)d_in[0];
    const float* bundles = (const float*)d_in[1];
    const float* items   = (const float*)d_in[2];
    const int*   ub_rows = (const int*)d_in[3];
    const int*   ub_cols = (const int*)d_in[4];
    const float* ub_vals = (const float*)d_in[5];
    const int*   ui_rows = (const int*)d_in[6];
    const int*   ui_cols = (const int*)d_in[7];
    const float* ui_vals = (const float*)d_in[8];
    const int*   bi_rows = (const int*)d_in[9];
    const int*   bi_cols = (const int*)d_in[10];
    const float* bi_vals = (const float*)d_in[11];
    const int*   bi_agg_rows = (const int*)d_in[12];
    const int*   bi_agg_cols = (const int*)d_in[13];
    const float* bi_agg_vals = (const float*)d_in[14];
    const int*   ui_agg_rows = (const int*)d_in[15];
    const int*   ui_agg_cols = (const int*)d_in[16];
    const float* ui_agg_vals = (const float*)d_in[17];
    const float* ub_coefs  = (const float*)d_in[18];
    const float* ui_coefs  = (const float*)d_in[19];
    const float* bi_coefs  = (const float*)d_in[20];
    const float* modal     = (const float*)d_in[21];

    int nE[5] = { in_sizes[3], in_sizes[6], in_sizes[9], in_sizes[15], in_sizes[12] };
    int nN[5] = { NU + NB, NU + NI, NB + NI, NU, NB };

    float *ub_f1, *ub_f2, *ui_f1, *ui_f2, *bi_f1, *bi_f2;
    float *ub_acc, *ui_acc, *bi_acc;
    int *cnt, *rowptr, *partials;
    int2* colval;
    cudaGetSymbolAddress((void**)&ub_f1,    g_ub_f1);
    cudaGetSymbolAddress((void**)&ub_f2,    g_ub_f2);
    cudaGetSymbolAddress((void**)&ui_f1,    g_ui_f1);
    cudaGetSymbolAddress((void**)&ui_f2,    g_ui_f2);
    cudaGetSymbolAddress((void**)&bi_f1,    g_bi_f1);
    cudaGetSymbolAddress((void**)&bi_f2,    g_bi_f2);
    cudaGetSymbolAddress((void**)&ub_acc,   g_ub_acc);
    cudaGetSymbolAddress((void**)&ui_acc,   g_ui_acc);
    cudaGetSymbolAddress((void**)&bi_acc,   g_bi_acc);
    cudaGetSymbolAddress((void**)&cnt,      g_cnt);
    cudaGetSymbolAddress((void**)&rowptr,   g_rowptr);
    cudaGetSymbolAddress((void**)&colval,   g_colval);
    cudaGetSymbolAddress((void**)&partials, g_partials);

    float* out = (float*)d_out;
    const int TB = 256;

    // Side streams + events: created once, on the first call (the correctness
    // run, outside graph capture). Capture-time usage is only record/wait.
    static cudaStream_t s1 = nullptr, s2 = nullptr;
    static cudaEvent_t ev_start, ev_build, ev0, ev1, ev2, ev_ob;
    if (s1 == nullptr) {
        cudaStreamCreateWithFlags(&s1, cudaStreamNonBlocking);
        cudaStreamCreateWithFlags(&s2, cudaStreamNonBlocking);
        cudaEventCreateWithFlags(&ev_start, cudaEventDisableTiming);
        cudaEventCreateWithFlags(&ev_build, cudaEventDisableTiming);
        cudaEventCreateWithFlags(&ev0, cudaEventDisableTiming);
        cudaEventCreateWithFlags(&ev1, cudaEventDisableTiming);
        cudaEventCreateWithFlags(&ev2, cudaEventDisableTiming);
        cudaEventCreateWithFlags(&ev_ob, cudaEventDisableTiming);
    }

    GraphSet gs;
    gs.rows[0] = ub_rows;     gs.cols[0] = ub_cols;     gs.vals[0] = ub_vals;
    gs.rows[1] = ui_rows;     gs.cols[1] = ui_cols;     gs.vals[1] = ui_vals;
    gs.rows[2] = bi_rows;     gs.cols[2] = bi_cols;     gs.vals[2] = bi_vals;
    gs.rows[3] = ui_agg_rows; gs.cols[3] = ui_agg_cols; gs.vals[3] = ui_agg_vals;
    gs.rows[4] = bi_agg_rows; gs.cols[4] = bi_agg_cols; gs.vals[4] = bi_agg_vals;
    gs.e_base[0] = 0; gs.n_base[0] = 0;
    for (int g = 0; g < 5; g++) {
        gs.e_base[g + 1] = gs.e_base[g] + nE[g];
        gs.n_base[g + 1] = gs.n_base[g] + nN[g];
    }
    int tot_e = gs.e_base[5];
    int tot_n = gs.n_base[5];
    int nblk = ceil_div(tot_n, SCAN_TB);

    // ---- fork: bring s1/s2 into the captured DAG ----
    cudaEventRecord(ev_start, 0);
    cudaStreamWaitEvent(s1, ev_start, 0);
    cudaStreamWaitEvent(s2, ev_start, 0);

    // ---- inits for UI/BI run concurrently with the CSR build ----
    k_init<<<ceil_div((NU + NI) * D4, TB), TB, 0, s1>>>(
        (const float4*)users, (const float4*)items, NU * D4, (NU + NI) * D4,
        ui_coefs, (float4*)ui_f1, (float4*)ui_acc);
    k_init<<<ceil_div((NB + NI) * D4, TB), TB, 0, s2>>>(
        (const float4*)bundles, (const float4*)items, NB * D4, (NB + NI) * D4,
        bi_coefs, (float4*)bi_f1, (float4*)bi_acc);

    // ---- CSR build on s0 ----
    k_zero_int<<<ceil_div(tot_n, TB), TB>>>(cnt, tot_n);
    {
        int stride = ceil_div(tot_e, 2);
        k_hist_all<<<ceil_div(stride, TB), TB>>>(gs, tot_e, stride, cnt);
    }
    k_partial<<<nblk, SCAN_TB>>>(cnt, tot_n, partials);
    k_scan_partials<<<1, MAX_BLKS>>>(partials, nblk);
    k_scan_final<<<nblk, SCAN_TB>>>(cnt, tot_n, partials, rowptr);
    {
        int stride = ceil_div(tot_e, 4);
        k_scatter_all<<<ceil_div(stride, TB), TB>>>(gs, tot_e, stride, cnt, colval);
    }
    cudaEventRecord(ev_build, 0);

    // ---- UB prop on s0 (after build) ----
    {
        int n_nodes = NU + NB;
        k_init<<<ceil_div(n_nodes * D4, TB), TB>>>(
            (const float4*)users, (const float4*)bundles, NU * D4, n_nodes * D4,
            ub_coefs, (float4*)ub_f1, (float4*)ub_acc);
        const int* rp = rowptr + gs.n_base[0];
        int blocks = ceil_div(n_nodes * 32, TB);
        k_spmm_csr<<<blocks, TB>>>(rp, colval, (const float4*)ub_f1, n_nodes,
                                   (float4*)ub_f2, (float4*)ub_acc, ub_coefs, 1);
        k_spmm_csr<<<blocks, TB>>>(rp, colval, (const float4*)ub_f2, n_nodes,
                                   (float4*)ub_f1, (float4*)ub_acc, ub_coefs, 2);
    }
    cudaEventRecord(ev0, 0);

    // ---- UI prop on s1 ----
    cudaStreamWaitEvent(s1, ev_build, 0);
    {
        int n_nodes = NU + NI;
        const int* rp = rowptr + gs.n_base[1];
        int blocks = ceil_div(n_nodes * 32, TB);
        k_spmm_csr<<<blocks, TB, 0, s1>>>(rp, colval, (const float4*)ui_f1, n_nodes,
                                          (float4*)ui_f2, (float4*)ui_acc, ui_coefs, 1);
        k_spmm_csr<<<blocks, TB, 0, s1>>>(rp, colval, (const float4*)ui_f2, n_nodes,
                                          (float4*)ui_f1, (float4*)ui_acc, ui_coefs, 2);
    }
    cudaEventRecord(ev1, s1);

    // ---- BI prop on s2 ----
    cudaStreamWaitEvent(s2, ev_build, 0);
    {
        int n_nodes = NB + NI;
        const int* rp = rowptr + gs.n_base[2];
        int blocks = ceil_div(n_nodes * 32, TB);
        k_spmm_csr<<<blocks, TB, 0, s2>>>(rp, colval, (const float4*)bi_f1, n_nodes,
                                          (float4*)bi_f2, (float4*)bi_acc, bi_coefs, 1);
        k_spmm_csr<<<blocks, TB, 0, s2>>>(rp, colval, (const float4*)bi_f2, n_nodes,
                                          (float4*)bi_f1, (float4*)bi_acc, bi_coefs, 2);
    }
    cudaEventRecord(ev2, s2);

    // ---- out_bundles on s1 (needs ub_acc, bi_acc; ui_acc implicit) ----
    cudaStreamWaitEvent(s1, ev0, 0);
    cudaStreamWaitEvent(s1, ev2, 0);
    k_out_bundles<<<ceil_div(NB * 32, TB), TB, 0, s1>>>(
        rowptr + gs.n_base[4], colval,
        (const float4*)ui_acc, (const float4*)ub_acc, (const float4*)bi_acc,
        modal, (float4*)out);
    cudaEventRecord(ev_ob, s1);

    // ---- out_users on s0 (needs ui_acc, bi_acc; ub_acc implicit) ----
    cudaStreamWaitEvent(0, ev1, 0);
    cudaStreamWaitEvent(0, ev2, 0);
    k_out_users<<<ceil_div(NU * 32, TB), TB>>>(
        rowptr + gs.n_base[3], colval,
        (const float4*)bi_acc, (const float4*)ub_acc, (const float4*)ui_acc,
        modal, (float4*)out);

    // ---- join everything back to s0 before returning ----
    cudaStreamWaitEvent(0, ev_ob, 0);
}

// round 17
// speedup vs baseline: 1.0608x; 1.0608x over previous
#include <cuda_runtime.h>
#include <cuda_fp16.h>

#define D 64
#define D4 16   // float4s per row

static const int NU = 30000, NB = 10000, NI = 60000;

// Concatenated node space: UB(40000) | UI(90000) | BI(70000) | UIagg(30000) | BIagg(10000)
#define TOT_NODES 240000
#define TOT_EDGES 5600000
#define SCAN_TB 512
#define MAX_BLKS 512

// Static device scratch (allocation-free rule).
// Propagation features in fp16 (halves L2 gather bytes); accumulators fp32.
__device__ __half g_feat [90000 * 64];
__device__ __half g_feat2[90000 * 64];
__device__ float  g_ub_acc[40000 * 64];
__device__ float  g_ui_acc[90000 * 64];
__device__ float  g_bi_acc[70000 * 64];
__device__ int    g_cnt   [TOT_NODES];
__device__ int    g_rowptr[TOT_NODES + 1];
__device__ int2   g_colval[TOT_EDGES];
__device__ int    g_partials[MAX_BLKS];

struct GraphSet {
    const int*   rows[5];
    const int*   cols[5];
    const float* vals[5];
    int e_base[6];
    int n_base[6];
};

// ---------------------------------------------------------------------------
__global__ void k_zero_int(int* __restrict__ p, int n) {
    int i = blockIdx.x * blockDim.x + threadIdx.x;
    if (i < n) p[i] = 0;
}

// One edge per thread (validated-fastest variant).
__global__ void k_hist_all(GraphSet gs, int tot_e, int* __restrict__ cnt) {
    int i = blockIdx.x * blockDim.x + threadIdx.x;
    if (i >= tot_e) return;
    int g = 0;
    #pragma unroll
    for (int k = 1; k < 5; k++) if (i >= gs.e_base[k]) g = k;
    int ei = i - gs.e_base[g];
    atomicAdd(&cnt[gs.n_base[g] + gs.rows[g][ei]], 1);
}

__global__ void k_partial(const int* __restrict__ cnt, int n, int* __restrict__ partials) {
    __shared__ int s[SCAN_TB];
    int i = blockIdx.x * SCAN_TB + threadIdx.x;
    int t = threadIdx.x;
    s[t] = (i < n) ? cnt[i] : 0;
    __syncthreads();
    for (int o = SCAN_TB / 2; o; o >>= 1) {
        if (t < o) s[t] += s[t + o];
        __syncthreads();
    }
    if (t == 0) partials[blockIdx.x] = s[0];
}

__global__ void k_scan_partials(int* __restrict__ p, int nblk) {
    __shared__ int s[MAX_BLKS];
    int t = threadIdx.x;
    s[t] = (t < nblk) ? p[t] : 0;
    __syncthreads();
    for (int o = 1; o < MAX_BLKS; o <<= 1) {
        int v = (t >= o) ? s[t - o] : 0;
        __syncthreads();
        s[t] += v;
        __syncthreads();
    }
    if (t < nblk) p[t] = (t ? s[t - 1] : 0);
}

__global__ void k_scan_final(int* __restrict__ cnt, int n,
                             const int* __restrict__ partials, int* __restrict__ rowptr) {
    __shared__ int s[SCAN_TB];
    int i = blockIdx.x * SCAN_TB + threadIdx.x;
    int t = threadIdx.x;
    int c = (i < n) ? cnt[i] : 0;
    s[t] = c;
    __syncthreads();
    for (int o = 1; o < SCAN_TB; o <<= 1) {
        int v = (t >= o) ? s[t - o] : 0;
        __syncthreads();
        s[t] += v;
        __syncthreads();
    }
    int start = partials[blockIdx.x] + s[t] - c;   // exclusive
    if (i < n) {
        rowptr[i] = start;
        cnt[i] = start;
        if (i == n - 1) rowptr[n] = start + c;
    }
}

// One edge per thread (validated-fastest variant).
__global__ void k_scatter_all(GraphSet gs, int tot_e,
                              int* __restrict__ pos, int2* __restrict__ colval) {
    int i = blockIdx.x * blockDim.x + threadIdx.x;
    if (i >= tot_e) return;
    int g = 0;
    #pragma unroll
    for (int k = 1; k < 5; k++) if (i >= gs.e_base[k]) g = k;
    int ei = i - gs.e_base[g];
    int p = atomicAdd(&pos[gs.n_base[g] + gs.rows[g][ei]], 1);
    colval[p] = make_int2(gs.cols[g][ei], __float_as_int(gs.vals[g][ei]));
}

// ---------------------------------------------------------------------------
__device__ __forceinline__ float4 ld_half4(const uint2* __restrict__ p, int idx) {
    uint2 u = __ldg(p + idx);
    __half2 h0 = *reinterpret_cast<__half2*>(&u.x);
    __half2 h1 = *reinterpret_cast<__half2*>(&u.y);
    float2 f0 = __half22float2(h0);
    float2 f1 = __half22float2(h1);
    return make_float4(f0.x, f0.y, f1.x, f1.y);
}

__device__ __forceinline__ uint2 pack_half4(float4 v) {
    __half2 h0 = __floats2half2_rn(v.x, v.y);
    __half2 h1 = __floats2half2_rn(v.z, v.w);
    uint2 u;
    u.x = *reinterpret_cast<unsigned*>(&h0);
    u.y = *reinterpret_cast<unsigned*>(&h1);
    return u;
}

__device__ __forceinline__ void fma4(float4& a, float v, float4 x) {
    a.x += v * x.x; a.y += v * x.y; a.z += v * x.z; a.w += v * x.w;
}

// feat(fp16) = concat(a, b); acc(fp32) = coefs[0] * feat
__global__ void k_init(const float4* __restrict__ a, const float4* __restrict__ b,
                       int na_v4, int tot_v4,
                       const float* __restrict__ coefs,
                       uint2* __restrict__ feat, float4* __restrict__ acc) {
    int i = blockIdx.x * blockDim.x + threadIdx.x;
    if (i >= tot_v4) return;
    float4 v = (i < na_v4) ? a[i] : b[i - na_v4];
    float c = coefs[0];
    feat[i] = pack_half4(v);
    acc[i] = make_float4(c * v.x, c * v.y, c * v.z, c * v.w);
}

// Row-parallel CSR SpMM fused with l2norm accumulation. One warp per row,
// halves take alternating edges, unroll x4 for gather MLP. fp16 gathers,
// fp32 accumulation; writes fp16 feat_out + fp32 acc update.
__global__ void k_spmm_csr(const int* __restrict__ rowptr, const int2* __restrict__ colval,
                           const uint2* __restrict__ feat, int n_rows,
                           uint2* __restrict__ feat_out, float4* __restrict__ acc_buf,
                           const float* __restrict__ coefs, int li) {
    int w   = (blockIdx.x * blockDim.x + threadIdx.x) >> 5;
    int lid = threadIdx.x & 31;
    if (w >= n_rows) return;
    int half = lid >> 4, q = lid & 15;
    int s = rowptr[w], e = rowptr[w + 1];
    float4 a0 = make_float4(0.f, 0.f, 0.f, 0.f);
    float4 a1 = make_float4(0.f, 0.f, 0.f, 0.f);
    int j = s + half;
    for (; j + 6 < e; j += 8) {
        int2 c0 = colval[j], c1 = colval[j + 2], c2 = colval[j + 4], c3 = colval[j + 6];
        float4 x0 = ld_half4(feat, c0.x * D4 + q);
        float4 x1 = ld_half4(feat, c1.x * D4 + q);
        float4 x2 = ld_half4(feat, c2.x * D4 + q);
        float4 x3 = ld_half4(feat, c3.x * D4 + q);
        fma4(a0, __int_as_float(c0.y), x0);
        fma4(a1, __int_as_float(c1.y), x1);
        fma4(a0, __int_as_float(c2.y), x2);
        fma4(a1, __int_as_float(c3.y), x3);
    }
    for (; j < e; j += 2) {
        int2 cv = colval[j];
        fma4(a0, __int_as_float(cv.y), ld_half4(feat, cv.x * D4 + q));
    }
    float4 acc = make_float4(a0.x + a1.x, a0.y + a1.y, a0.z + a1.z, a0.w + a1.w);
    acc.x += __shfl_xor_sync(0xffffffffu, acc.x, 16);
    acc.y += __shfl_xor_sync(0xffffffffu, acc.y, 16);
    acc.z += __shfl_xor_sync(0xffffffffu, acc.z, 16);
    acc.w += __shfl_xor_sync(0xffffffffu, acc.w, 16);
    float ss = acc.x * acc.x + acc.y * acc.y + acc.z * acc.z + acc.w * acc.w;
    #pragma unroll
    for (int o = 8; o; o >>= 1) ss += __shfl_xor_sync(0xffffffffu, ss, o);
    float k = coefs[li] / fmaxf(sqrtf(ss), 1e-12f);
    if (half == 0) {
        int idx = w * D4 + q;
        feat_out[idx] = pack_half4(acc);
        float4 a = acc_buf[idx];
        a.x += k * acc.x; a.y += k * acc.y; a.z += k * acc.z; a.w += k * acc.w;
        acc_buf[idx] = a;
    }
}

// out[user row] = m0*ub_acc + m1*ui_acc + m2 * sum_edges(v * bi_acc_items[col])
__global__ void k_out_users(const int* __restrict__ rowptr, const int2* __restrict__ colval,
                            const float4* __restrict__ bi_acc,
                            const float4* __restrict__ ub_acc,
                            const float4* __restrict__ ui_acc,
                            const float* __restrict__ modal, float4* __restrict__ out) {
    int w   = (blockIdx.x * blockDim.x + threadIdx.x) >> 5;
    int lid = threadIdx.x & 31;
    if (w >= NU) return;
    int half = lid >> 4, q = lid & 15;
    int s = rowptr[w], e = rowptr[w + 1];
    float4 a0 = make_float4(0.f, 0.f, 0.f, 0.f);
    float4 a1 = make_float4(0.f, 0.f, 0.f, 0.f);
    int j = s + half;
    for (; j + 6 < e; j += 8) {
        int2 c0 = colval[j], c1 = colval[j + 2], c2 = colval[j + 4], c3 = colval[j + 6];
        float4 x0 = bi_acc[(NB + c0.x) * D4 + q];
        float4 x1 = bi_acc[(NB + c1.x) * D4 + q];
        float4 x2 = bi_acc[(NB + c2.x) * D4 + q];
        float4 x3 = bi_acc[(NB + c3.x) * D4 + q];
        fma4(a0, __int_as_float(c0.y), x0);
        fma4(a1, __int_as_float(c1.y), x1);
        fma4(a0, __int_as_float(c2.y), x2);
        fma4(a1, __int_as_float(c3.y), x3);
    }
    for (; j < e; j += 2) {
        int2 cv = colval[j];
        fma4(a0, __int_as_float(cv.y), bi_acc[(NB + cv.x) * D4 + q]);
    }
    float4 agg = make_float4(a0.x + a1.x, a0.y + a1.y, a0.z + a1.z, a0.w + a1.w);
    agg.x += __shfl_xor_sync(0xffffffffu, agg.x, 16);
    agg.y += __shfl_xor_sync(0xffffffffu, agg.y, 16);
    agg.z += __shfl_xor_sync(0xffffffffu, agg.z, 16);
    agg.w += __shfl_xor_sync(0xffffffffu, agg.w, 16);
    if (half == 0) {
        float m0 = modal[0], m1 = modal[1], m2 = modal[2];
        int idx = w * D4 + q;
        float4 u = ub_acc[idx];
        float4 t = ui_acc[idx];
        out[idx] = make_float4(m0 * u.x + m1 * t.x + m2 * agg.x,
                               m0 * u.y + m1 * t.y + m2 * agg.y,
                               m0 * u.z + m1 * t.z + m2 * agg.z,
                               m0 * u.w + m1 * t.w + m2 * agg.w);
    }
}

// out[NU+row] = m0*ub_acc_bundles + m2*bi_acc_bundles + m1 * sum(v * ui_acc_items[col])
__global__ void k_out_bundles(const int* __restrict__ rowptr, const int2* __restrict__ colval,
                              const float4* __restrict__ ui_acc,
                              const float4* __restrict__ ub_acc,
                              const float4* __restrict__ bi_acc,
                              const float* __restrict__ modal, float4* __restrict__ out) {
    int w   = (blockIdx.x * blockDim.x + threadIdx.x) >> 5;
    int lid = threadIdx.x & 31;
    if (w >= NB) return;
    int half = lid >> 4, q = lid & 15;
    int s = rowptr[w], e = rowptr[w + 1];
    float4 a0 = make_float4(0.f, 0.f, 0.f, 0.f);
    float4 a1 = make_float4(0.f, 0.f, 0.f, 0.f);
    int j = s + half;
    for (; j + 6 < e; j += 8) {
        int2 c0 = colval[j], c1 = colval[j + 2], c2 = colval[j + 4], c3 = colval[j + 6];
        float4 x0 = ui_acc[(NU + c0.x) * D4 + q];
        float4 x1 = ui_acc[(NU + c1.x) * D4 + q];
        float4 x2 = ui_acc[(NU + c2.x) * D4 + q];
        float4 x3 = ui_acc[(NU + c3.x) * D4 + q];
        fma4(a0, __int_as_float(c0.y), x0);
        fma4(a1, __int_as_float(c1.y), x1);
        fma4(a0, __int_as_float(c2.y), x2);
        fma4(a1, __int_as_float(c3.y), x3);
    }
    for (; j < e; j += 2) {
        int2 cv = colval[j];
        fma4(a0, __int_as_float(cv.y), ui_acc[(NU + cv.x) * D4 + q]);
    }
    float4 agg = make_float4(a0.x + a1.x, a0.y + a1.y, a0.z + a1.z, a0.w + a1.w);
    agg.x += __shfl_xor_sync(0xffffffffu, agg.x, 16);
    agg.y += __shfl_xor_sync(0xffffffffu, agg.y, 16);
    agg.z += __shfl_xor_sync(0xffffffffu, agg.z, 16);
    agg.w += __shfl_xor_sync(0xffffffffu, agg.w, 16);
    if (half == 0) {
        float m0 = modal[0], m1 = modal[1], m2 = modal[2];
        float4 u = ub_acc[(NU + w) * D4 + q];
        float4 t = bi_acc[w * D4 + q];
        out[(NU + w) * D4 + q] =
            make_float4(m0 * u.x + m2 * t.x + m1 * agg.x,
                        m0 * u.y + m2 * t.y + m1 * agg.y,
                        m0 * u.z + m2 * t.z + m1 * agg.z,
                        m0 * u.w + m2 * t.w + m1 * agg.w);
    }
}

// ---------------------------------------------------------------------------
static inline int ceil_div(int a, int b) { return (a + b - 1) / b; }

extern "C" void kernel_launch(void* const* d_in, const int* in_sizes, int n_in,
                              void* d_out, int out_size) {
    const float* users   = (const float*)d_in[0];
    const float* bundles = (const float*)d_in[1];
    const float* items   = (const float*)d_in[2];
    const int*   ub_rows = (const int*)d_in[3];
    const int*   ub_cols = (const int*)d_in[4];
    const float* ub_vals = (const float*)d_in[5];
    const int*   ui_rows = (const int*)d_in[6];
    const int*   ui_cols = (const int*)d_in[7];
    const float* ui_vals = (const float*)d_in[8];
    const int*   bi_rows = (const int*)d_in[9];
    const int*   bi_cols = (const int*)d_in[10];
    const float* bi_vals = (const float*)d_in[11];
    const int*   bi_agg_rows = (const int*)d_in[12];
    const int*   bi_agg_cols = (const int*)d_in[13];
    const float* bi_agg_vals = (const float*)d_in[14];
    const int*   ui_agg_rows = (const int*)d_in[15];
    const int*   ui_agg_cols = (const int*)d_in[16];
    const float* ui_agg_vals = (const float*)d_in[17];
    const float* ub_coefs  = (const float*)d_in[18];
    const float* ui_coefs  = (const float*)d_in[19];
    const float* bi_coefs  = (const float*)d_in[20];
    const float* modal     = (const float*)d_in[21];

    int nE[5] = { in_sizes[3], in_sizes[6], in_sizes[9], in_sizes[15], in_sizes[12] };
    int nN[5] = { NU + NB, NU + NI, NB + NI, NU, NB };

    __half *feat, *feat2;
    float *ub_acc, *ui_acc, *bi_acc;
    int *cnt, *rowptr, *partials;
    int2* colval;
    cudaGetSymbolAddress((void**)&feat,     g_feat);
    cudaGetSymbolAddress((void**)&feat2,    g_feat2);
    cudaGetSymbolAddress((void**)&ub_acc,   g_ub_acc);
    cudaGetSymbolAddress((void**)&ui_acc,   g_ui_acc);
    cudaGetSymbolAddress((void**)&bi_acc,   g_bi_acc);
    cudaGetSymbolAddress((void**)&cnt,      g_cnt);
    cudaGetSymbolAddress((void**)&rowptr,   g_rowptr);
    cudaGetSymbolAddress((void**)&colval,   g_colval);
    cudaGetSymbolAddress((void**)&partials, g_partials);

    float* out = (float*)d_out;
    const int TB = 256;

    GraphSet gs;
    gs.rows[0] = ub_rows;     gs.cols[0] = ub_cols;     gs.vals[0] = ub_vals;
    gs.rows[1] = ui_rows;     gs.cols[1] = ui_cols;     gs.vals[1] = ui_vals;
    gs.rows[2] = bi_rows;     gs.cols[2] = bi_cols;     gs.vals[2] = bi_vals;
    gs.rows[3] = ui_agg_rows; gs.cols[3] = ui_agg_cols; gs.vals[3] = ui_agg_vals;
    gs.rows[4] = bi_agg_rows; gs.cols[4] = bi_agg_cols; gs.vals[4] = bi_agg_vals;
    gs.e_base[0] = 0; gs.n_base[0] = 0;
    for (int g = 0; g < 5; g++) {
        gs.e_base[g + 1] = gs.e_base[g] + nE[g];
        gs.n_base[g + 1] = gs.n_base[g] + nN[g];
    }
    int tot_e = gs.e_base[5];
    int tot_n = gs.n_base[5];
    int nblk = ceil_div(tot_n, SCAN_TB);

    // ---- single batched CSR build for all 5 graphs ----
    k_zero_int<<<ceil_div(tot_n, TB), TB>>>(cnt, tot_n);
    k_hist_all<<<ceil_div(tot_e, TB), TB>>>(gs, tot_e, cnt);
    k_partial<<<nblk, SCAN_TB>>>(cnt, tot_n, partials);
    k_scan_partials<<<1, MAX_BLKS>>>(partials, nblk);
    k_scan_final<<<nblk, SCAN_TB>>>(cnt, tot_n, partials, rowptr);
    k_scatter_all<<<ceil_div(tot_e, TB), TB>>>(gs, tot_e, cnt, colval);

    // ---- three propagations (per-graph: working set stays L2-resident) ----
    struct Prop {
        const float *a, *b; int na, nb;
        const float* coefs; float* acc; int gidx;
    } props[3] = {
        { users,   bundles, NU, NB, ub_coefs, ub_acc, 0 },
        { users,   items,   NU, NI, ui_coefs, ui_acc, 1 },
        { bundles, items,   NB, NI, bi_coefs, bi_acc, 2 },
    };
    for (int g = 0; g < 3; g++) {
        Prop& p = props[g];
        int n_nodes = p.na + p.nb;
        int n_v4 = n_nodes * D4;
        const int* rp = rowptr + gs.n_base[p.gidx];
        k_init<<<ceil_div(n_v4, TB), TB>>>((const float4*)p.a, (const float4*)p.b,
                                           p.na * D4, n_v4, p.coefs,
                                           (uint2*)feat, (float4*)p.acc);
        int blocks = ceil_div(n_nodes * 32, TB);
        k_spmm_csr<<<blocks, TB>>>(rp, colval, (const uint2*)feat, n_nodes,
                                   (uint2*)feat2, (float4*)p.acc, p.coefs, 1);
        k_spmm_csr<<<blocks, TB>>>(rp, colval, (const uint2*)feat2, n_nodes,
                                   (uint2*)feat, (float4*)p.acc, p.coefs, 2);
    }

    // ---- fused combine + aggregation outputs (fp32 gathers from acc) ----
    k_out_users<<<ceil_div(NU * 32, TB), TB>>>(rowptr + gs.n_base[3], colval,
                                               (const float4*)bi_acc,
                                               (const float4*)ub_acc, (const float4*)ui_acc,
                                               modal, (float4*)out);
    k_out_bundles<<<ceil_div(NB * 32, TB), TB>>>(rowptr + gs.n_base[4], colval,
                                                 (const float4*)ui_acc,
                                                 (const float4*)ub_acc, (const float4*)bi_acc,
                                                 modal, (float4*)out);
}